// round 1
// baseline (speedup 1.0000x reference)
#include <cuda_runtime.h>
#include <math.h>

#define N_TOKENS 16384
#define D_MODEL  1024
#define D_FF     2048
#define N_EXPERTS 4

// ---------------- scratch (device globals; no allocation allowed) ----------------
__device__ int   g_cnt[N_EXPERTS];
__device__ int   g_tok[N_EXPERTS * N_TOKENS];
__device__ float g_wgt[N_EXPERTS * N_TOKENS];
__device__ float g_H[(size_t)N_EXPERTS * N_TOKENS * D_FF];     // 512 MB
__device__ float g_Z[(size_t)N_EXPERTS * N_TOKENS * D_MODEL];  // 256 MB

__device__ __forceinline__ float gelu_exact(float v) {
    return 0.5f * v * (1.0f + erff(v * 0.70710678118654752440f));
}

// ---------------- init ----------------
__global__ void init_counts_kernel() {
    if (threadIdx.x < N_EXPERTS) g_cnt[threadIdx.x] = 0;
}

// ---------------- gating: scores, top-2, softmax, compaction ----------------
__global__ void __launch_bounds__(256) gate_kernel(const float* __restrict__ x,
                                                   const float* __restrict__ gate_w) {
    __shared__ float sgw[N_EXPERTS * D_MODEL];
    const int tid = threadIdx.x;
    for (int i = tid; i < N_EXPERTS * D_MODEL; i += 256) sgw[i] = gate_w[i];
    __syncthreads();

    const int warp = tid >> 5, lane = tid & 31;
    const int tok = blockIdx.x * 8 + warp;
    if (tok >= N_TOKENS) return;

    const float* xr = x + (size_t)tok * D_MODEL;
    float acc0 = 0.f, acc1 = 0.f, acc2 = 0.f, acc3 = 0.f;
    for (int k = lane; k < D_MODEL; k += 32) {
        float xv = xr[k];
        acc0 += xv * sgw[0 * D_MODEL + k];
        acc1 += xv * sgw[1 * D_MODEL + k];
        acc2 += xv * sgw[2 * D_MODEL + k];
        acc3 += xv * sgw[3 * D_MODEL + k];
    }
    #pragma unroll
    for (int o = 16; o; o >>= 1) {
        acc0 += __shfl_xor_sync(0xffffffffu, acc0, o);
        acc1 += __shfl_xor_sync(0xffffffffu, acc1, o);
        acc2 += __shfl_xor_sync(0xffffffffu, acc2, o);
        acc3 += __shfl_xor_sync(0xffffffffu, acc3, o);
    }
    if (lane == 0) {
        float s[4] = {acc0, acc1, acc2, acc3};
        int i0 = 0;
        #pragma unroll
        for (int e = 1; e < 4; e++) if (s[e] > s[i0]) i0 = e;   // first max (ties -> low idx)
        int i1 = -1;
        #pragma unroll
        for (int e = 0; e < 4; e++) {
            if (e == i0) continue;
            if (i1 < 0 || s[e] > s[i1]) i1 = e;
        }
        float t  = expf(s[i1] - s[i0]);
        float p0 = 1.0f / (1.0f + t);
        float p1 = t / (1.0f + t);

        int p = atomicAdd(&g_cnt[i0], 1);
        g_tok[i0 * N_TOKENS + p] = tok;
        g_wgt[i0 * N_TOKENS + p] = p0;
        p = atomicAdd(&g_cnt[i1], 1);
        g_tok[i1 * N_TOKENS + p] = tok;
        g_wgt[i1 * N_TOKENS + p] = p1;
    }
}

// ---------------- GEMM1: H = gelu(gather(X) @ W1e^T + b1e) ----------------
// tile 128x128, K-tile 16, 256 threads, 8x8 per thread
__global__ void __launch_bounds__(256) gemm1_kernel(const float* __restrict__ x,
                                                    const float* __restrict__ w1,
                                                    const float* __restrict__ b1) {
    const int e   = blockIdx.z;
    const int cnt = g_cnt[e];
    const int m0  = blockIdx.y * 128;
    if (m0 >= cnt) return;
    const int n0  = blockIdx.x * 128;

    __shared__ float As[16][128];
    __shared__ float Bs[16][128];
    __shared__ int   stok[128];

    const int tid = threadIdx.x;
    if (tid < 128) {
        int m = m0 + tid;
        stok[tid] = (m < cnt) ? g_tok[e * N_TOKENS + m] : -1;
    }
    __syncthreads();

    const float* Wb = w1 + (size_t)e * D_FF * D_MODEL + (size_t)n0 * D_MODEL;

    const int ty = tid >> 4;      // 0..15
    const int tx = tid & 15;      // 0..15
    const int am  = tid >> 2;     // 0..63 (plus +64 slab)
    const int akq = (tid & 3) * 4;

    const int r0 = stok[am];
    const int r1 = stok[am + 64];
    const float* a0p = x + (size_t)(r0 < 0 ? 0 : r0) * D_MODEL + akq;
    const float* a1p = x + (size_t)(r1 < 0 ? 0 : r1) * D_MODEL + akq;
    const float* b0p = Wb + (size_t)am * D_MODEL + akq;
    const float* b1p_ = Wb + (size_t)(am + 64) * D_MODEL + akq;

    float acc[8][8];
    #pragma unroll
    for (int i = 0; i < 8; i++)
        #pragma unroll
        for (int j = 0; j < 8; j++) acc[i][j] = 0.f;

    for (int kt = 0; kt < D_MODEL; kt += 16) {
        float4 av0 = make_float4(0.f, 0.f, 0.f, 0.f), av1 = av0;
        if (r0 >= 0) av0 = *(const float4*)(a0p + kt);
        if (r1 >= 0) av1 = *(const float4*)(a1p + kt);
        float4 bv0 = *(const float4*)(b0p + kt);
        float4 bv1 = *(const float4*)(b1p_ + kt);

        __syncthreads();
        As[akq + 0][am] = av0.x; As[akq + 1][am] = av0.y;
        As[akq + 2][am] = av0.z; As[akq + 3][am] = av0.w;
        As[akq + 0][am + 64] = av1.x; As[akq + 1][am + 64] = av1.y;
        As[akq + 2][am + 64] = av1.z; As[akq + 3][am + 64] = av1.w;
        Bs[akq + 0][am] = bv0.x; Bs[akq + 1][am] = bv0.y;
        Bs[akq + 2][am] = bv0.z; Bs[akq + 3][am] = bv0.w;
        Bs[akq + 0][am + 64] = bv1.x; Bs[akq + 1][am + 64] = bv1.y;
        Bs[akq + 2][am + 64] = bv1.z; Bs[akq + 3][am + 64] = bv1.w;
        __syncthreads();

        #pragma unroll
        for (int k = 0; k < 16; k++) {
            float a[8], b[8];
            #pragma unroll
            for (int i = 0; i < 8; i++) a[i] = As[k][ty * 8 + i];
            #pragma unroll
            for (int j = 0; j < 8; j++) b[j] = Bs[k][tx * 8 + j];
            #pragma unroll
            for (int i = 0; i < 8; i++)
                #pragma unroll
                for (int j = 0; j < 8; j++) acc[i][j] += a[i] * b[j];
        }
    }

    const float* bias = b1 + (size_t)e * D_FF + n0 + tx * 8;
    #pragma unroll
    for (int i = 0; i < 8; i++) {
        int m = m0 + ty * 8 + i;
        if (m >= cnt) continue;
        float* Hrow = g_H + ((size_t)e * N_TOKENS + m) * D_FF + n0 + tx * 8;
        #pragma unroll
        for (int j = 0; j < 8; j += 4) {
            float4 v;
            v.x = gelu_exact(acc[i][j + 0] + bias[j + 0]);
            v.y = gelu_exact(acc[i][j + 1] + bias[j + 1]);
            v.z = gelu_exact(acc[i][j + 2] + bias[j + 2]);
            v.w = gelu_exact(acc[i][j + 3] + bias[j + 3]);
            *(float4*)(Hrow + j) = v;
        }
    }
}

// ---------------- GEMM2: Z = x + H @ W2e^T + b2e ----------------
__global__ void __launch_bounds__(256) gemm2_kernel(const float* __restrict__ x,
                                                    const float* __restrict__ w2,
                                                    const float* __restrict__ b2) {
    const int e   = blockIdx.z;
    const int cnt = g_cnt[e];
    const int m0  = blockIdx.y * 128;
    if (m0 >= cnt) return;
    const int n0  = blockIdx.x * 128;

    __shared__ float As[16][128];
    __shared__ float Bs[16][128];
    __shared__ int   stok[128];

    const int tid = threadIdx.x;
    if (tid < 128) {
        int m = m0 + tid;
        stok[tid] = (m < cnt) ? g_tok[e * N_TOKENS + m] : -1;
    }
    __syncthreads();

    const float* Wb = w2 + (size_t)e * D_MODEL * D_FF + (size_t)n0 * D_FF;

    const int ty = tid >> 4;
    const int tx = tid & 15;
    const int am  = tid >> 2;
    const int akq = (tid & 3) * 4;

    const bool v0 = (m0 + am)      < cnt;
    const bool v1 = (m0 + am + 64) < cnt;
    const float* a0p = g_H + ((size_t)e * N_TOKENS + m0 + am)      * D_FF + akq;
    const float* a1p = g_H + ((size_t)e * N_TOKENS + m0 + am + 64) * D_FF + akq;
    const float* b0p = Wb + (size_t)am * D_FF + akq;
    const float* b1p_ = Wb + (size_t)(am + 64) * D_FF + akq;

    float acc[8][8];
    #pragma unroll
    for (int i = 0; i < 8; i++)
        #pragma unroll
        for (int j = 0; j < 8; j++) acc[i][j] = 0.f;

    for (int kt = 0; kt < D_FF; kt += 16) {
        float4 av0 = make_float4(0.f, 0.f, 0.f, 0.f), av1 = av0;
        if (v0) av0 = *(const float4*)(a0p + kt);
        if (v1) av1 = *(const float4*)(a1p + kt);
        float4 bv0 = *(const float4*)(b0p + kt);
        float4 bv1 = *(const float4*)(b1p_ + kt);

        __syncthreads();
        As[akq + 0][am] = av0.x; As[akq + 1][am] = av0.y;
        As[akq + 2][am] = av0.z; As[akq + 3][am] = av0.w;
        As[akq + 0][am + 64] = av1.x; As[akq + 1][am + 64] = av1.y;
        As[akq + 2][am + 64] = av1.z; As[akq + 3][am + 64] = av1.w;
        Bs[akq + 0][am] = bv0.x; Bs[akq + 1][am] = bv0.y;
        Bs[akq + 2][am] = bv0.z; Bs[akq + 3][am] = bv0.w;
        Bs[akq + 0][am + 64] = bv1.x; Bs[akq + 1][am + 64] = bv1.y;
        Bs[akq + 2][am + 64] = bv1.z; Bs[akq + 3][am + 64] = bv1.w;
        __syncthreads();

        #pragma unroll
        for (int k = 0; k < 16; k++) {
            float a[8], b[8];
            #pragma unroll
            for (int i = 0; i < 8; i++) a[i] = As[k][ty * 8 + i];
            #pragma unroll
            for (int j = 0; j < 8; j++) b[j] = Bs[k][tx * 8 + j];
            #pragma unroll
            for (int i = 0; i < 8; i++)
                #pragma unroll
                for (int j = 0; j < 8; j++) acc[i][j] += a[i] * b[j];
        }
    }

    const float* bias = b2 + (size_t)e * D_MODEL + n0 + tx * 8;
    #pragma unroll
    for (int i = 0; i < 8; i++) {
        int m = m0 + ty * 8 + i;
        if (m >= cnt) continue;
        int tok = stok[ty * 8 + i];
        const float* xr = x + (size_t)tok * D_MODEL + n0 + tx * 8;
        float* Zrow = g_Z + ((size_t)e * N_TOKENS + m) * D_MODEL + n0 + tx * 8;
        #pragma unroll
        for (int j = 0; j < 8; j += 4) {
            float4 xv = *(const float4*)(xr + j);
            float4 v;
            v.x = acc[i][j + 0] + bias[j + 0] + xv.x;
            v.y = acc[i][j + 1] + bias[j + 1] + xv.y;
            v.z = acc[i][j + 2] + bias[j + 2] + xv.z;
            v.w = acc[i][j + 3] + bias[j + 3] + xv.w;
            *(float4*)(Zrow + j) = v;
        }
    }
}

// ---------------- LayerNorm + gamma/beta + weighted scatter-add ----------------
__global__ void __launch_bounds__(256) ln_kernel(const float* __restrict__ gamma,
                                                 const float* __restrict__ beta,
                                                 float* __restrict__ out) {
    const int e    = blockIdx.y;
    const int slot = blockIdx.x;
    if (slot >= g_cnt[e]) return;

    const int   tok = g_tok[e * N_TOKENS + slot];
    const float w   = g_wgt[e * N_TOKENS + slot];
    const float* z  = g_Z + ((size_t)e * N_TOKENS + slot) * D_MODEL;

    const int tid  = threadIdx.x;
    const int lane = tid & 31, warp = tid >> 5;

    __shared__ float red1[8];
    __shared__ float red2[8];

    float4 v = ((const float4*)z)[tid];

    float s = v.x + v.y + v.z + v.w;
    #pragma unroll
    for (int o = 16; o; o >>= 1) s += __shfl_xor_sync(0xffffffffu, s, o);
    if (lane == 0) red1[warp] = s;
    __syncthreads();
    float tot = 0.f;
    #pragma unroll
    for (int i = 0; i < 8; i++) tot += red1[i];
    const float mu = tot * (1.0f / D_MODEL);

    float dx = v.x - mu, dy = v.y - mu, dz = v.z - mu, dw = v.w - mu;
    float sq = dx * dx + dy * dy + dz * dz + dw * dw;
    #pragma unroll
    for (int o = 16; o; o >>= 1) sq += __shfl_xor_sync(0xffffffffu, sq, o);
    if (lane == 0) red2[warp] = sq;
    __syncthreads();
    float tot2 = 0.f;
    #pragma unroll
    for (int i = 0; i < 8; i++) tot2 += red2[i];
    const float var  = tot2 * (1.0f / D_MODEL);
    const float rstd = rsqrtf(var + 1e-6f);

    float4 g  = ((const float4*)(gamma + (size_t)e * D_MODEL))[tid];
    float4 bb = ((const float4*)(beta  + (size_t)e * D_MODEL))[tid];

    float* o = out + (size_t)tok * D_MODEL + tid * 4;
    atomicAdd(o + 0, w * (dx * rstd * g.x + bb.x));
    atomicAdd(o + 1, w * (dy * rstd * g.y + bb.y));
    atomicAdd(o + 2, w * (dz * rstd * g.z + bb.z));
    atomicAdd(o + 3, w * (dw * rstd * g.w + bb.w));
}

// ---------------- launch ----------------
extern "C" void kernel_launch(void* const* d_in, const int* in_sizes, int n_in,
                              void* d_out, int out_size) {
    const float* x      = (const float*)d_in[0];
    const float* gate_w = (const float*)d_in[1];
    const float* w1     = (const float*)d_in[2];
    const float* b1     = (const float*)d_in[3];
    const float* w2     = (const float*)d_in[4];
    const float* b2     = (const float*)d_in[5];
    const float* gamma  = (const float*)d_in[6];
    const float* beta   = (const float*)d_in[7];
    float* out = (float*)d_out;

    cudaMemsetAsync(d_out, 0, (size_t)out_size * sizeof(float), 0);
    init_counts_kernel<<<1, 32>>>();
    gate_kernel<<<N_TOKENS / 8, 256>>>(x, gate_w);

    dim3 g1(D_FF / 128, N_TOKENS / 128, N_EXPERTS);
    gemm1_kernel<<<g1, 256>>>(x, w1, b1);

    dim3 g2(D_MODEL / 128, N_TOKENS / 128, N_EXPERTS);
    gemm2_kernel<<<g2, 256>>>(x, w2, b2);

    dim3 g3(N_TOKENS, N_EXPERTS);
    ln_kernel<<<g3, 256>>>(gamma, beta, out);
}

// round 2
// speedup vs baseline: 3.7867x; 3.7867x over previous
#include <cuda_runtime.h>
#include <math.h>
#include <stdint.h>

#define N_TOKENS 16384
#define D_MODEL  1024
#define D_FF     2048
#define N_EXPERTS 4

// ---------------- scratch (device globals; no allocation allowed) ----------------
__device__ int   g_cnt[N_EXPERTS];
__device__ int   g_tok[N_EXPERTS * N_TOKENS];
__device__ float g_wgt[N_EXPERTS * N_TOKENS];
__device__ float g_H[(size_t)N_EXPERTS * N_TOKENS * D_FF];     // 512 MB
__device__ float g_Z[(size_t)N_EXPERTS * N_TOKENS * D_MODEL];  // 256 MB

__device__ __forceinline__ float gelu_exact(float v) {
    return 0.5f * v * (1.0f + erff(v * 0.70710678118654752440f));
}

__device__ __forceinline__ uint32_t f2tf32(float x) {
    uint32_t r;
    asm("cvt.rna.tf32.f32 %0, %1;" : "=r"(r) : "f"(x));
    return r;
}

__device__ __forceinline__ void mma_tf32(float c[4], const uint32_t a[4], const uint32_t b[2]) {
    asm volatile(
        "mma.sync.aligned.m16n8k8.row.col.f32.tf32.tf32.f32 "
        "{%0,%1,%2,%3}, {%4,%5,%6,%7}, {%8,%9}, {%0,%1,%2,%3};"
        : "+f"(c[0]), "+f"(c[1]), "+f"(c[2]), "+f"(c[3])
        : "r"(a[0]), "r"(a[1]), "r"(a[2]), "r"(a[3]), "r"(b[0]), "r"(b[1]));
}

// ---------------- init ----------------
__global__ void init_counts_kernel() {
    if (threadIdx.x < N_EXPERTS) g_cnt[threadIdx.x] = 0;
}

// ---------------- gating: scores, top-2, softmax, compaction ----------------
__global__ void __launch_bounds__(256) gate_kernel(const float* __restrict__ x,
                                                   const float* __restrict__ gate_w) {
    __shared__ float sgw[N_EXPERTS * D_MODEL];
    const int tid = threadIdx.x;
    for (int i = tid; i < N_EXPERTS * D_MODEL; i += 256) sgw[i] = gate_w[i];
    __syncthreads();

    const int warp = tid >> 5, lane = tid & 31;
    const int tok = blockIdx.x * 8 + warp;
    if (tok >= N_TOKENS) return;

    const float* xr = x + (size_t)tok * D_MODEL;
    float acc0 = 0.f, acc1 = 0.f, acc2 = 0.f, acc3 = 0.f;
    for (int k = lane; k < D_MODEL; k += 32) {
        float xv = xr[k];
        acc0 += xv * sgw[0 * D_MODEL + k];
        acc1 += xv * sgw[1 * D_MODEL + k];
        acc2 += xv * sgw[2 * D_MODEL + k];
        acc3 += xv * sgw[3 * D_MODEL + k];
    }
    #pragma unroll
    for (int o = 16; o; o >>= 1) {
        acc0 += __shfl_xor_sync(0xffffffffu, acc0, o);
        acc1 += __shfl_xor_sync(0xffffffffu, acc1, o);
        acc2 += __shfl_xor_sync(0xffffffffu, acc2, o);
        acc3 += __shfl_xor_sync(0xffffffffu, acc3, o);
    }
    if (lane == 0) {
        float s[4] = {acc0, acc1, acc2, acc3};
        int i0 = 0;
        #pragma unroll
        for (int e = 1; e < 4; e++) if (s[e] > s[i0]) i0 = e;
        int i1 = -1;
        #pragma unroll
        for (int e = 0; e < 4; e++) {
            if (e == i0) continue;
            if (i1 < 0 || s[e] > s[i1]) i1 = e;
        }
        float t  = expf(s[i1] - s[i0]);
        float p0 = 1.0f / (1.0f + t);
        float p1 = t / (1.0f + t);

        int p = atomicAdd(&g_cnt[i0], 1);
        g_tok[i0 * N_TOKENS + p] = tok;
        g_wgt[i0 * N_TOKENS + p] = p0;
        p = atomicAdd(&g_cnt[i1], 1);
        g_tok[i1 * N_TOKENS + p] = tok;
        g_wgt[i1 * N_TOKENS + p] = p1;
    }
}

// ======================= TF32 tensor-core GEMMs =======================
// Tile 128x128, BK=32, 256 threads = 8 warps (2 M x 4 N), warp tile 64x32.
// Fragments per warp: 4 (M) x 4 (N) m16n8k8 tiles, 4 k-steps per K-tile.
#define BK 32
#define SPAD 36   // smem row stride (uint32) -> conflict-free fragment reads

// GEMM1: H = gelu(gather(X) @ W1e^T + b1e)
__global__ void __launch_bounds__(256) gemm1_kernel(const float* __restrict__ x,
                                                    const float* __restrict__ w1,
                                                    const float* __restrict__ b1) {
    const int e   = blockIdx.z;
    const int cnt = g_cnt[e];
    const int m0  = blockIdx.y * 128;
    if (m0 >= cnt) return;
    const int n0  = blockIdx.x * 128;

    __shared__ uint32_t As[128][SPAD];
    __shared__ uint32_t Bs[128][SPAD];
    __shared__ int stok[128];

    const int tid = threadIdx.x;
    if (tid < 128) {
        int m = m0 + tid;
        stok[tid] = (m < cnt) ? g_tok[e * N_TOKENS + m] : -1;
    }
    __syncthreads();

    const int lr = tid >> 3;        // loader row base 0..31
    const int lq = (tid & 7) * 4;   // loader k offset (quad)

    const int warp = tid >> 5, lane = tid & 31;
    const int wm = (warp & 1) * 64;
    const int wn = (warp >> 1) * 32;
    const int gid = lane >> 2, tig = lane & 3;

    const float* Wb = w1 + (size_t)e * D_FF * D_MODEL + (size_t)n0 * D_MODEL;

    // loader source rows (A gathered by token, B = W rows)
    int   arow[4]; const float* aptr[4]; const float* bptr[4];
    #pragma unroll
    for (int i = 0; i < 4; i++) {
        arow[i] = lr + 32 * i;
        int t = stok[arow[i]];
        aptr[i] = x + (size_t)(t < 0 ? 0 : t) * D_MODEL + lq;
        bptr[i] = Wb + (size_t)(lr + 32 * i) * D_MODEL + lq;
    }
    bool aval[4];
    #pragma unroll
    for (int i = 0; i < 4; i++) aval[i] = (stok[arow[i]] >= 0);

    float acc[4][4][4];
    #pragma unroll
    for (int mt = 0; mt < 4; mt++)
        #pragma unroll
        for (int nt = 0; nt < 4; nt++)
            #pragma unroll
            for (int r = 0; r < 4; r++) acc[mt][nt][r] = 0.f;

    for (int kt = 0; kt < D_MODEL; kt += BK) {
        float4 av[4], bv[4];
        #pragma unroll
        for (int i = 0; i < 4; i++) {
            av[i] = aval[i] ? *(const float4*)(aptr[i] + kt)
                            : make_float4(0.f, 0.f, 0.f, 0.f);
            bv[i] = *(const float4*)(bptr[i] + kt);
        }
        __syncthreads();
        #pragma unroll
        for (int i = 0; i < 4; i++) {
            uint32_t* ad = &As[lr + 32 * i][lq];
            ad[0] = f2tf32(av[i].x); ad[1] = f2tf32(av[i].y);
            ad[2] = f2tf32(av[i].z); ad[3] = f2tf32(av[i].w);
            uint32_t* bd = &Bs[lr + 32 * i][lq];
            bd[0] = f2tf32(bv[i].x); bd[1] = f2tf32(bv[i].y);
            bd[2] = f2tf32(bv[i].z); bd[3] = f2tf32(bv[i].w);
        }
        __syncthreads();

        #pragma unroll
        for (int ks = 0; ks < 4; ks++) {
            const int kc = ks * 8 + tig;
            uint32_t af[4][4], bf[4][2];
            #pragma unroll
            for (int mt = 0; mt < 4; mt++) {
                int r = wm + mt * 16 + gid;
                af[mt][0] = As[r][kc];     af[mt][1] = As[r + 8][kc];
                af[mt][2] = As[r][kc + 4]; af[mt][3] = As[r + 8][kc + 4];
            }
            #pragma unroll
            for (int nt = 0; nt < 4; nt++) {
                int c = wn + nt * 8 + gid;
                bf[nt][0] = Bs[c][kc]; bf[nt][1] = Bs[c][kc + 4];
            }
            #pragma unroll
            for (int mt = 0; mt < 4; mt++)
                #pragma unroll
                for (int nt = 0; nt < 4; nt++)
                    mma_tf32(acc[mt][nt], af[mt], bf[nt]);
        }
    }

    // epilogue: bias + exact GELU -> g_H
    #pragma unroll
    for (int nt = 0; nt < 4; nt++) {
        const int nl = wn + nt * 8 + tig * 2;
        float2 bb = *(const float2*)(b1 + (size_t)e * D_FF + n0 + nl);
        #pragma unroll
        for (int mt = 0; mt < 4; mt++) {
            int mA = m0 + wm + mt * 16 + gid;
            if (mA < cnt) {
                float2 v;
                v.x = gelu_exact(acc[mt][nt][0] + bb.x);
                v.y = gelu_exact(acc[mt][nt][1] + bb.y);
                *(float2*)(g_H + ((size_t)e * N_TOKENS + mA) * D_FF + n0 + nl) = v;
            }
            int mB = mA + 8;
            if (mB < cnt) {
                float2 v;
                v.x = gelu_exact(acc[mt][nt][2] + bb.x);
                v.y = gelu_exact(acc[mt][nt][3] + bb.y);
                *(float2*)(g_H + ((size_t)e * N_TOKENS + mB) * D_FF + n0 + nl) = v;
            }
        }
    }
}

// GEMM2: Z = x + H @ W2e^T + b2e
__global__ void __launch_bounds__(256) gemm2_kernel(const float* __restrict__ x,
                                                    const float* __restrict__ w2,
                                                    const float* __restrict__ b2) {
    const int e   = blockIdx.z;
    const int cnt = g_cnt[e];
    const int m0  = blockIdx.y * 128;
    if (m0 >= cnt) return;
    const int n0  = blockIdx.x * 128;

    __shared__ uint32_t As[128][SPAD];
    __shared__ uint32_t Bs[128][SPAD];
    __shared__ int stok[128];

    const int tid = threadIdx.x;
    if (tid < 128) {
        int m = m0 + tid;
        stok[tid] = (m < cnt) ? g_tok[e * N_TOKENS + m] : -1;
    }
    __syncthreads();

    const int lr = tid >> 3;
    const int lq = (tid & 7) * 4;

    const int warp = tid >> 5, lane = tid & 31;
    const int wm = (warp & 1) * 64;
    const int wn = (warp >> 1) * 32;
    const int gid = lane >> 2, tig = lane & 3;

    const float* Wb = w2 + (size_t)e * D_MODEL * D_FF + (size_t)n0 * D_FF;

    const float* aptr[4]; const float* bptr[4]; bool aval[4];
    #pragma unroll
    for (int i = 0; i < 4; i++) {
        int r = lr + 32 * i;
        aval[i] = (m0 + r) < cnt;
        aptr[i] = g_H + ((size_t)e * N_TOKENS + m0 + r) * D_FF + lq;
        bptr[i] = Wb + (size_t)r * D_FF + lq;
    }

    float acc[4][4][4];
    #pragma unroll
    for (int mt = 0; mt < 4; mt++)
        #pragma unroll
        for (int nt = 0; nt < 4; nt++)
            #pragma unroll
            for (int r = 0; r < 4; r++) acc[mt][nt][r] = 0.f;

    for (int kt = 0; kt < D_FF; kt += BK) {
        float4 av[4], bv[4];
        #pragma unroll
        for (int i = 0; i < 4; i++) {
            av[i] = aval[i] ? *(const float4*)(aptr[i] + kt)
                            : make_float4(0.f, 0.f, 0.f, 0.f);
            bv[i] = *(const float4*)(bptr[i] + kt);
        }
        __syncthreads();
        #pragma unroll
        for (int i = 0; i < 4; i++) {
            uint32_t* ad = &As[lr + 32 * i][lq];
            ad[0] = f2tf32(av[i].x); ad[1] = f2tf32(av[i].y);
            ad[2] = f2tf32(av[i].z); ad[3] = f2tf32(av[i].w);
            uint32_t* bd = &Bs[lr + 32 * i][lq];
            bd[0] = f2tf32(bv[i].x); bd[1] = f2tf32(bv[i].y);
            bd[2] = f2tf32(bv[i].z); bd[3] = f2tf32(bv[i].w);
        }
        __syncthreads();

        #pragma unroll
        for (int ks = 0; ks < 4; ks++) {
            const int kc = ks * 8 + tig;
            uint32_t af[4][4], bf[4][2];
            #pragma unroll
            for (int mt = 0; mt < 4; mt++) {
                int r = wm + mt * 16 + gid;
                af[mt][0] = As[r][kc];     af[mt][1] = As[r + 8][kc];
                af[mt][2] = As[r][kc + 4]; af[mt][3] = As[r + 8][kc + 4];
            }
            #pragma unroll
            for (int nt = 0; nt < 4; nt++) {
                int c = wn + nt * 8 + gid;
                bf[nt][0] = Bs[c][kc]; bf[nt][1] = Bs[c][kc + 4];
            }
            #pragma unroll
            for (int mt = 0; mt < 4; mt++)
                #pragma unroll
                for (int nt = 0; nt < 4; nt++)
                    mma_tf32(acc[mt][nt], af[mt], bf[nt]);
        }
    }

    // epilogue: bias + residual -> g_Z
    #pragma unroll
    for (int nt = 0; nt < 4; nt++) {
        const int nl = wn + nt * 8 + tig * 2;
        float2 bb = *(const float2*)(b2 + (size_t)e * D_MODEL + n0 + nl);
        #pragma unroll
        for (int mt = 0; mt < 4; mt++) {
            int mA = m0 + wm + mt * 16 + gid;
            if (mA < cnt) {
                int tok = stok[wm + mt * 16 + gid];
                float2 xv = *(const float2*)(x + (size_t)tok * D_MODEL + n0 + nl);
                float2 v;
                v.x = acc[mt][nt][0] + bb.x + xv.x;
                v.y = acc[mt][nt][1] + bb.y + xv.y;
                *(float2*)(g_Z + ((size_t)e * N_TOKENS + mA) * D_MODEL + n0 + nl) = v;
            }
            int mB = mA + 8;
            if (mB < cnt) {
                int tok = stok[wm + mt * 16 + gid + 8];
                float2 xv = *(const float2*)(x + (size_t)tok * D_MODEL + n0 + nl);
                float2 v;
                v.x = acc[mt][nt][2] + bb.x + xv.x;
                v.y = acc[mt][nt][3] + bb.y + xv.y;
                *(float2*)(g_Z + ((size_t)e * N_TOKENS + mB) * D_MODEL + n0 + nl) = v;
            }
        }
    }
}

// ---------------- LayerNorm + gamma/beta + weighted scatter-add ----------------
__global__ void __launch_bounds__(256) ln_kernel(const float* __restrict__ gamma,
                                                 const float* __restrict__ beta,
                                                 float* __restrict__ out) {
    const int e    = blockIdx.y;
    const int slot = blockIdx.x;
    if (slot >= g_cnt[e]) return;

    const int   tok = g_tok[e * N_TOKENS + slot];
    const float w   = g_wgt[e * N_TOKENS + slot];
    const float* z  = g_Z + ((size_t)e * N_TOKENS + slot) * D_MODEL;

    const int tid  = threadIdx.x;
    const int lane = tid & 31, warp = tid >> 5;

    __shared__ float red1[8];
    __shared__ float red2[8];

    float4 v = ((const float4*)z)[tid];

    float s = v.x + v.y + v.z + v.w;
    #pragma unroll
    for (int o = 16; o; o >>= 1) s += __shfl_xor_sync(0xffffffffu, s, o);
    if (lane == 0) red1[warp] = s;
    __syncthreads();
    float tot = 0.f;
    #pragma unroll
    for (int i = 0; i < 8; i++) tot += red1[i];
    const float mu = tot * (1.0f / D_MODEL);

    float dx = v.x - mu, dy = v.y - mu, dz = v.z - mu, dw = v.w - mu;
    float sq = dx * dx + dy * dy + dz * dz + dw * dw;
    #pragma unroll
    for (int o = 16; o; o >>= 1) sq += __shfl_xor_sync(0xffffffffu, sq, o);
    if (lane == 0) red2[warp] = sq;
    __syncthreads();
    float tot2 = 0.f;
    #pragma unroll
    for (int i = 0; i < 8; i++) tot2 += red2[i];
    const float var  = tot2 * (1.0f / D_MODEL);
    const float rstd = rsqrtf(var + 1e-6f);

    float4 g  = ((const float4*)(gamma + (size_t)e * D_MODEL))[tid];
    float4 bb = ((const float4*)(beta  + (size_t)e * D_MODEL))[tid];

    float* o = out + (size_t)tok * D_MODEL + tid * 4;
    atomicAdd(o + 0, w * (dx * rstd * g.x + bb.x));
    atomicAdd(o + 1, w * (dy * rstd * g.y + bb.y));
    atomicAdd(o + 2, w * (dz * rstd * g.z + bb.z));
    atomicAdd(o + 3, w * (dw * rstd * g.w + bb.w));
}

// ---------------- launch ----------------
extern "C" void kernel_launch(void* const* d_in, const int* in_sizes, int n_in,
                              void* d_out, int out_size) {
    const float* x      = (const float*)d_in[0];
    const float* gate_w = (const float*)d_in[1];
    const float* w1     = (const float*)d_in[2];
    const float* b1     = (const float*)d_in[3];
    const float* w2     = (const float*)d_in[4];
    const float* b2     = (const float*)d_in[5];
    const float* gamma  = (const float*)d_in[6];
    const float* beta   = (const float*)d_in[7];
    float* out = (float*)d_out;

    cudaMemsetAsync(d_out, 0, (size_t)out_size * sizeof(float), 0);
    init_counts_kernel<<<1, 32>>>();
    gate_kernel<<<N_TOKENS / 8, 256>>>(x, gate_w);

    dim3 g1(D_FF / 128, N_TOKENS / 128, N_EXPERTS);
    gemm1_kernel<<<g1, 256>>>(x, w1, b1);

    dim3 g2(D_MODEL / 128, N_TOKENS / 128, N_EXPERTS);
    gemm2_kernel<<<g2, 256>>>(x, w2, b2);

    dim3 g3(N_TOKENS, N_EXPERTS);
    ln_kernel<<<g3, 256>>>(gamma, beta, out);
}

// round 4
// speedup vs baseline: 5.7316x; 1.5136x over previous
#include <cuda_runtime.h>
#include <math.h>
#include <stdint.h>

#define N_TOKENS 16384
#define D_MODEL  1024
#define D_FF     2048
#define N_EXPERTS 4

// ---------------- scratch (device globals; no allocation allowed) ----------------
__device__ int   g_cnt[N_EXPERTS];
__device__ int   g_tok[N_EXPERTS * N_TOKENS];
__device__ float g_wgt[N_EXPERTS * N_TOKENS];
__device__ float g_H[(size_t)N_EXPERTS * N_TOKENS * D_FF];     // 512 MB
__device__ float g_Z[(size_t)N_EXPERTS * N_TOKENS * D_MODEL];  // 256 MB

__device__ __forceinline__ float gelu_exact(float v) {
    return 0.5f * v * (1.0f + erff(v * 0.70710678118654752440f));
}

__device__ __forceinline__ void mma_tf32(float c[4], const uint32_t a[4], const uint32_t b[2]) {
    asm volatile(
        "mma.sync.aligned.m16n8k8.row.col.f32.tf32.tf32.f32 "
        "{%0,%1,%2,%3}, {%4,%5,%6,%7}, {%8,%9}, {%0,%1,%2,%3};"
        : "+f"(c[0]), "+f"(c[1]), "+f"(c[2]), "+f"(c[3])
        : "r"(a[0]), "r"(a[1]), "r"(a[2]), "r"(a[3]), "r"(b[0]), "r"(b[1]));
}

__device__ __forceinline__ uint32_t smem_u32(const void* p) {
    uint32_t a;
    asm("{ .reg .u64 t; cvta.to.shared.u64 t, %1; cvt.u32.u64 %0, t; }" : "=r"(a) : "l"(p));
    return a;
}
__device__ __forceinline__ void cpasync16(uint32_t dst, const void* src) {
    asm volatile("cp.async.cg.shared.global [%0], [%1], 16;" :: "r"(dst), "l"(src));
}
__device__ __forceinline__ void cp_commit() {
    asm volatile("cp.async.commit_group;" ::: "memory");
}
__device__ __forceinline__ void cp_wait1() {
    asm volatile("cp.async.wait_group 1;" ::: "memory");
}
__device__ __forceinline__ void cp_wait0() {
    asm volatile("cp.async.wait_group 0;" ::: "memory");
}

// ---------------- init ----------------
__global__ void init_counts_kernel() {
    if (threadIdx.x < N_EXPERTS) g_cnt[threadIdx.x] = 0;
}

// ---------------- gating: scores, top-2, softmax, compaction ----------------
__global__ void __launch_bounds__(256) gate_kernel(const float* __restrict__ x,
                                                   const float* __restrict__ gate_w) {
    __shared__ float sgw[N_EXPERTS * D_MODEL];
    const int tid = threadIdx.x;
    for (int i = tid; i < N_EXPERTS * D_MODEL; i += 256) sgw[i] = gate_w[i];
    __syncthreads();

    const int warp = tid >> 5, lane = tid & 31;
    const int tok = blockIdx.x * 8 + warp;
    if (tok >= N_TOKENS) return;

    const float* xr = x + (size_t)tok * D_MODEL;
    float acc0 = 0.f, acc1 = 0.f, acc2 = 0.f, acc3 = 0.f;
    for (int k = lane; k < D_MODEL; k += 32) {
        float xv = xr[k];
        acc0 += xv * sgw[0 * D_MODEL + k];
        acc1 += xv * sgw[1 * D_MODEL + k];
        acc2 += xv * sgw[2 * D_MODEL + k];
        acc3 += xv * sgw[3 * D_MODEL + k];
    }
    #pragma unroll
    for (int o = 16; o; o >>= 1) {
        acc0 += __shfl_xor_sync(0xffffffffu, acc0, o);
        acc1 += __shfl_xor_sync(0xffffffffu, acc1, o);
        acc2 += __shfl_xor_sync(0xffffffffu, acc2, o);
        acc3 += __shfl_xor_sync(0xffffffffu, acc3, o);
    }
    if (lane == 0) {
        float s[4] = {acc0, acc1, acc2, acc3};
        int i0 = 0;
        #pragma unroll
        for (int e = 1; e < 4; e++) if (s[e] > s[i0]) i0 = e;
        int i1 = -1;
        #pragma unroll
        for (int e = 0; e < 4; e++) {
            if (e == i0) continue;
            if (i1 < 0 || s[e] > s[i1]) i1 = e;
        }
        float t  = expf(s[i1] - s[i0]);
        float p0 = 1.0f / (1.0f + t);
        float p1 = t / (1.0f + t);

        int p = atomicAdd(&g_cnt[i0], 1);
        g_tok[i0 * N_TOKENS + p] = tok;
        g_wgt[i0 * N_TOKENS + p] = p0;
        p = atomicAdd(&g_cnt[i1], 1);
        g_tok[i1 * N_TOKENS + p] = tok;
        g_wgt[i1 * N_TOKENS + p] = p1;
    }
}

// ======================= TF32 tensor-core GEMMs (cp.async pipelined) =======================
// Tile 128x128, BK=32, 256 threads = 8 warps (2 M x 4 N), warp tile 64x32.
// 3-stage cp.async pipeline, smem row stride 36 floats (conflict-free fragment LDS).
#define BK 32
#define SROW 36
#define STAGES 3
#define A_STAGE_F (128 * SROW)                 // floats
#define STAGE_F   (2 * A_STAGE_F)              // A + B
#define SMEM_DYN  (STAGES * STAGE_F * 4)       // bytes = 110592

template<int KDIM, bool G1>
__global__ void __launch_bounds__(256, 2) moe_gemm(
    const float* __restrict__ Asrc, const float* __restrict__ W,
    const float* __restrict__ bias, const float* __restrict__ resid)
{
    const int e   = blockIdx.z;
    const int cnt = g_cnt[e];
    const int m0  = blockIdx.y * 128;
    if (m0 >= cnt) return;
    const int n0  = blockIdx.x * 128;

    extern __shared__ float smem[];
    __shared__ int stok[128];

    const int tid = threadIdx.x;
    if (tid < 128) {
        int m = m0 + tid;
        stok[tid] = g_tok[e * N_TOKENS + (m < cnt ? m : cnt - 1)];
    }
    __syncthreads();

    // ---- loader mapping: 4 A-chunks + 4 B-chunks of 16B per thread per stage ----
    const int cj4  = (tid & 7) * 4;   // float offset within a 32-float row
    const int row0 = tid >> 3;        // 0..31

    const float* aptr[4];
    const float* bptr[4];
    uint32_t off16[4];
    #pragma unroll
    for (int i = 0; i < 4; i++) {
        const int row = row0 + 32 * i;
        if (G1) {
            aptr[i] = Asrc + (size_t)stok[row] * KDIM + cj4;
        } else {
            int mr = m0 + row; if (mr >= cnt) mr = cnt - 1;
            aptr[i] = Asrc + ((size_t)e * N_TOKENS + mr) * KDIM + cj4;
        }
        bptr[i] = W + (size_t)e * ((size_t)D_FF * D_MODEL) + (size_t)(n0 + row) * KDIM + cj4;
        off16[i] = (uint32_t)(row * SROW + cj4) * 4u;
    }

    const uint32_t sbase = smem_u32(smem);

    auto issue = [&](int t, int s) {
        const int kt = t * BK;
        const uint32_t sa = sbase + (uint32_t)s * (STAGE_F * 4);
        const uint32_t sb = sa + A_STAGE_F * 4;
        #pragma unroll
        for (int i = 0; i < 4; i++) {
            cpasync16(sa + off16[i], aptr[i] + kt);
            cpasync16(sb + off16[i], bptr[i] + kt);
        }
    };

    // ---- compute mapping ----
    const int warp = tid >> 5, lane = tid & 31;
    const int wm = (warp & 1) * 64;
    const int wn = (warp >> 1) * 32;
    const int gid = lane >> 2, tig = lane & 3;

    float acc[4][4][4];
    #pragma unroll
    for (int mt = 0; mt < 4; mt++)
        #pragma unroll
        for (int nt = 0; nt < 4; nt++)
            #pragma unroll
            for (int r = 0; r < 4; r++) acc[mt][nt][r] = 0.f;

    constexpr int T = KDIM / BK;

    issue(0, 0); cp_commit();
    issue(1, 1); cp_commit();

    for (int t = 0; t < T; t++) {
        const int s = t % STAGES;
        if (t + 2 < T) cp_wait1(); else cp_wait0();
        __syncthreads();
        if (t + 2 < T) { issue(t + 2, (t + 2) % STAGES); cp_commit(); }

        const float* As = smem + s * STAGE_F;
        const float* Bs = As + A_STAGE_F;

        #pragma unroll
        for (int ks = 0; ks < 4; ks++) {
            const int kc = ks * 8 + tig;
            uint32_t af[4][4], bf[4][2];
            #pragma unroll
            for (int mt = 0; mt < 4; mt++) {
                const int r = wm + mt * 16 + gid;
                af[mt][0] = __float_as_uint(As[r * SROW + kc]);
                af[mt][1] = __float_as_uint(As[(r + 8) * SROW + kc]);
                af[mt][2] = __float_as_uint(As[r * SROW + kc + 4]);
                af[mt][3] = __float_as_uint(As[(r + 8) * SROW + kc + 4]);
            }
            #pragma unroll
            for (int nt = 0; nt < 4; nt++) {
                const int c = wn + nt * 8 + gid;
                bf[nt][0] = __float_as_uint(Bs[c * SROW + kc]);
                bf[nt][1] = __float_as_uint(Bs[c * SROW + kc + 4]);
            }
            #pragma unroll
            for (int mt = 0; mt < 4; mt++)
                #pragma unroll
                for (int nt = 0; nt < 4; nt++)
                    mma_tf32(acc[mt][nt], af[mt], bf[nt]);
        }
        __syncthreads();
    }

    // ---- epilogue ----
    #pragma unroll
    for (int nt = 0; nt < 4; nt++) {
        const int nl = wn + nt * 8 + tig * 2;
        if (G1) {
            float2 bb = *(const float2*)(bias + (size_t)e * D_FF + n0 + nl);
            #pragma unroll
            for (int mt = 0; mt < 4; mt++) {
                int mA = m0 + wm + mt * 16 + gid;
                if (mA < cnt) {
                    float2 v;
                    v.x = gelu_exact(acc[mt][nt][0] + bb.x);
                    v.y = gelu_exact(acc[mt][nt][1] + bb.y);
                    *(float2*)(g_H + ((size_t)e * N_TOKENS + mA) * D_FF + n0 + nl) = v;
                }
                int mB = mA + 8;
                if (mB < cnt) {
                    float2 v;
                    v.x = gelu_exact(acc[mt][nt][2] + bb.x);
                    v.y = gelu_exact(acc[mt][nt][3] + bb.y);
                    *(float2*)(g_H + ((size_t)e * N_TOKENS + mB) * D_FF + n0 + nl) = v;
                }
            }
        } else {
            float2 bb = *(const float2*)(bias + (size_t)e * D_MODEL + n0 + nl);
            #pragma unroll
            for (int mt = 0; mt < 4; mt++) {
                int mA = m0 + wm + mt * 16 + gid;
                if (mA < cnt) {
                    int tok = stok[wm + mt * 16 + gid];
                    float2 xv = *(const float2*)(resid + (size_t)tok * D_MODEL + n0 + nl);
                    float2 v;
                    v.x = acc[mt][nt][0] + bb.x + xv.x;
                    v.y = acc[mt][nt][1] + bb.y + xv.y;
                    *(float2*)(g_Z + ((size_t)e * N_TOKENS + mA) * D_MODEL + n0 + nl) = v;
                }
                int mB = mA + 8;
                if (mB < cnt) {
                    int tok = stok[wm + mt * 16 + gid + 8];
                    float2 xv = *(const float2*)(resid + (size_t)tok * D_MODEL + n0 + nl);
                    float2 v;
                    v.x = acc[mt][nt][2] + bb.x + xv.x;
                    v.y = acc[mt][nt][3] + bb.y + xv.y;
                    *(float2*)(g_Z + ((size_t)e * N_TOKENS + mB) * D_MODEL + n0 + nl) = v;
                }
            }
        }
    }
}

// ---------------- LayerNorm + gamma/beta + weighted scatter-add ----------------
__global__ void __launch_bounds__(256) ln_kernel(const float* __restrict__ gamma,
                                                 const float* __restrict__ beta,
                                                 float* __restrict__ out) {
    const int e    = blockIdx.y;
    const int slot = blockIdx.x;
    if (slot >= g_cnt[e]) return;

    const int   tok = g_tok[e * N_TOKENS + slot];
    const float w   = g_wgt[e * N_TOKENS + slot];
    const float* z  = g_Z + ((size_t)e * N_TOKENS + slot) * D_MODEL;

    const int tid  = threadIdx.x;
    const int lane = tid & 31, warp = tid >> 5;

    __shared__ float red1[8];
    __shared__ float red2[8];

    float4 v = ((const float4*)z)[tid];

    float s = v.x + v.y + v.z + v.w;
    #pragma unroll
    for (int o = 16; o; o >>= 1) s += __shfl_xor_sync(0xffffffffu, s, o);
    if (lane == 0) red1[warp] = s;
    __syncthreads();
    float tot = 0.f;
    #pragma unroll
    for (int i = 0; i < 8; i++) tot += red1[i];
    const float mu = tot * (1.0f / D_MODEL);

    float dx = v.x - mu, dy = v.y - mu, dz = v.z - mu, dw = v.w - mu;
    float sq = dx * dx + dy * dy + dz * dz + dw * dw;
    #pragma unroll
    for (int o = 16; o; o >>= 1) sq += __shfl_xor_sync(0xffffffffu, sq, o);
    if (lane == 0) red2[warp] = sq;
    __syncthreads();
    float tot2 = 0.f;
    #pragma unroll
    for (int i = 0; i < 8; i++) tot2 += red2[i];
    const float var  = tot2 * (1.0f / D_MODEL);
    const float rstd = rsqrtf(var + 1e-6f);

    float4 g  = ((const float4*)(gamma + (size_t)e * D_MODEL))[tid];
    float4 bb = ((const float4*)(beta  + (size_t)e * D_MODEL))[tid];

    float* o = out + (size_t)tok * D_MODEL + tid * 4;
    atomicAdd(o + 0, w * (dx * rstd * g.x + bb.x));
    atomicAdd(o + 1, w * (dy * rstd * g.y + bb.y));
    atomicAdd(o + 2, w * (dz * rstd * g.z + bb.z));
    atomicAdd(o + 3, w * (dw * rstd * g.w + bb.w));
}

// ---------------- launch ----------------
extern "C" void kernel_launch(void* const* d_in, const int* in_sizes, int n_in,
                              void* d_out, int out_size) {
    const float* x      = (const float*)d_in[0];
    const float* gate_w = (const float*)d_in[1];
    const float* w1     = (const float*)d_in[2];
    const float* b1     = (const float*)d_in[3];
    const float* w2     = (const float*)d_in[4];
    const float* b2     = (const float*)d_in[5];
    const float* gamma  = (const float*)d_in[6];
    const float* beta   = (const float*)d_in[7];

    float* hptr = nullptr;
    cudaGetSymbolAddress((void**)&hptr, g_H);

    cudaFuncSetAttribute(moe_gemm<D_MODEL, true>,
                         cudaFuncAttributeMaxDynamicSharedMemorySize, SMEM_DYN);
    cudaFuncSetAttribute(moe_gemm<D_FF, false>,
                         cudaFuncAttributeMaxDynamicSharedMemorySize, SMEM_DYN);

    cudaMemsetAsync(d_out, 0, (size_t)out_size * sizeof(float), 0);
    init_counts_kernel<<<1, 32>>>();
    gate_kernel<<<N_TOKENS / 8, 256>>>(x, gate_w);

    dim3 g1(D_FF / 128, N_TOKENS / 128, N_EXPERTS);
    moe_gemm<D_MODEL, true><<<g1, 256, SMEM_DYN>>>(x, w1, b1, nullptr);

    dim3 g2(D_MODEL / 128, N_TOKENS / 128, N_EXPERTS);
    moe_gemm<D_FF, false><<<g2, 256, SMEM_DYN>>>(hptr, w2, b2, x);

    dim3 g3(N_TOKENS, N_EXPERTS);
    ln_kernel<<<g3, 256>>>(gamma, beta, (float*)d_out);
}